// round 3
// baseline (speedup 1.0000x reference)
#include <cuda_runtime.h>
#include <math.h>

// Problem constants
#define B_  4
#define L_  1024
#define E_  2048
#define H_  16
#define D_  128
#define BL_ (B_*L_)            // 4096
#define BH_ (B_*H_)            // 64
#define SCALE_ 0.08838834764831845f   // 1/sqrt(128)

// -------- scratch (device globals; no allocation allowed) --------
__device__ float g_Q[(size_t)BL_*E_];   // 32MB each
__device__ float g_K[(size_t)BL_*E_];
__device__ float g_V[(size_t)BL_*E_];
__device__ float g_O[(size_t)BL_*E_];
__device__ float g_S[(size_t)BH_*L_*L_]; // 256MB scores/probs

// ============================================================================
// Generic NT GEMM with bias: C[M,N] = A[M,K] @ B[N,K]^T + bias
// A,B row-major with leading dim K; C row-major leading dim N.
// Tile 128x128, BK=16, 256 threads, 8x8 per thread (split 2x 4-wide halves).
// M%128==0, N%128==0, K%16==0 for all uses — no bounds checks.
// ============================================================================
__global__ __launch_bounds__(256) void gemm_nt_bias(
    const float* __restrict__ A, const float* __restrict__ Bw,
    const float* __restrict__ bias, float* __restrict__ C,
    int M, int N, int K)
{
    __shared__ __align__(16) float As[16][128];
    __shared__ __align__(16) float Bs[16][128];
    const int tid = threadIdx.x;
    const int m0 = blockIdx.y * 128;
    const int n0 = blockIdx.x * 128;
    const int ty = tid >> 4, tx = tid & 15;
    const int lrow = tid >> 2, lq = tid & 3;

    float acc[8][8];
    #pragma unroll
    for (int i = 0; i < 8; i++)
        #pragma unroll
        for (int j = 0; j < 8; j++) acc[i][j] = 0.f;

    for (int k0 = 0; k0 < K; k0 += 16) {
        #pragma unroll
        for (int it = 0; it < 2; ++it) {
            int r = lrow + it * 64;
            float4 av = *(const float4*)(A + (size_t)(m0 + r) * K + k0 + lq * 4);
            As[lq*4+0][r] = av.x; As[lq*4+1][r] = av.y;
            As[lq*4+2][r] = av.z; As[lq*4+3][r] = av.w;
            float4 bv = *(const float4*)(Bw + (size_t)(n0 + r) * K + k0 + lq * 4);
            Bs[lq*4+0][r] = bv.x; Bs[lq*4+1][r] = bv.y;
            Bs[lq*4+2][r] = bv.z; Bs[lq*4+3][r] = bv.w;
        }
        __syncthreads();
        #pragma unroll
        for (int kk = 0; kk < 16; ++kk) {
            float4 a0 = *(const float4*)&As[kk][ty*4];
            float4 a1 = *(const float4*)&As[kk][64 + ty*4];
            float4 b0 = *(const float4*)&Bs[kk][tx*4];
            float4 b1 = *(const float4*)&Bs[kk][64 + tx*4];
            float a[8] = {a0.x,a0.y,a0.z,a0.w,a1.x,a1.y,a1.z,a1.w};
            float b[8] = {b0.x,b0.y,b0.z,b0.w,b1.x,b1.y,b1.z,b1.w};
            #pragma unroll
            for (int i = 0; i < 8; i++)
                #pragma unroll
                for (int j = 0; j < 8; j++)
                    acc[i][j] = fmaf(a[i], b[j], acc[i][j]);
        }
        __syncthreads();
    }
    #pragma unroll
    for (int ih = 0; ih < 2; ih++)
        #pragma unroll
        for (int ii = 0; ii < 4; ii++) {
            int m = m0 + ih*64 + ty*4 + ii;
            #pragma unroll
            for (int jh = 0; jh < 2; jh++) {
                int n = n0 + jh*64 + tx*4;
                float4 o;
                o.x = acc[ih*4+ii][jh*4+0] + bias[n+0];
                o.y = acc[ih*4+ii][jh*4+1] + bias[n+1];
                o.z = acc[ih*4+ii][jh*4+2] + bias[n+2];
                o.w = acc[ih*4+ii][jh*4+3] + bias[n+3];
                *(float4*)(C + (size_t)m * N + n) = o;
            }
        }
}

// ============================================================================
// Fused RMSNorm + rotary for Q and K. One warp per (b,l,h) head-vector (d=128).
// Layout is [b*l, h*128+dd]. Warps [0, BL*H) -> Q, [BL*H, 2*BL*H) -> K.
// ============================================================================
__global__ __launch_bounds__(256) void normrope_kernel(
    float* __restrict__ Q, float* __restrict__ Kb,
    const float* __restrict__ cosp, const float* __restrict__ sinp)
{
    int gw = blockIdx.x * 8 + (threadIdx.x >> 5);
    int lane = threadIdx.x & 31;
    float* X = (gw < BL_ * H_) ? Q : Kb;
    int w = gw % (BL_ * H_);
    int row = w / H_;          // b*L + i
    int h   = w % H_;
    int i   = row & (L_ - 1);  // sequence position
    float* x = X + (size_t)row * E_ + h * D_;

    float v0 = x[lane], v1 = x[lane+32], v2 = x[lane+64], v3 = x[lane+96];
    float ss = v0*v0 + v1*v1 + v2*v2 + v3*v3;
    #pragma unroll
    for (int o = 16; o; o >>= 1) ss += __shfl_xor_sync(0xffffffffu, ss, o);
    float r = rsqrtf(ss * (1.0f / 128.0f) + 1e-6f);
    v0 *= r; v1 *= r; v2 *= r; v3 *= r;

    // rotary: pairs (j, j+64). lane owns j=lane and j=lane+32.
    float c0 = cosp[i*64 + lane],      s0 = sinp[i*64 + lane];
    float c1 = cosp[i*64 + lane + 32], s1 = sinp[i*64 + lane + 32];
    x[lane]      = v0 * c0 - v2 * s0;
    x[lane + 64] = v0 * s0 + v2 * c0;
    x[lane + 32] = v1 * c1 - v3 * s1;
    x[lane + 96] = v1 * s1 + v3 * c1;
}

// ============================================================================
// Batched causal scores: S[bh, i, j] = (Q_h[i,:] . K_h[j,:]) / sqrt(d)
// Q/K rows have stride E (head chunk at h*128). Blocks fully above the
// diagonal are skipped (softmax never reads j > i).
// ============================================================================
__global__ __launch_bounds__(256) void scores_kernel(
    const float* __restrict__ Q, const float* __restrict__ Kb,
    float* __restrict__ S)
{
    const int bh = blockIdx.z;
    const int i0 = blockIdx.y * 128;
    const int j0 = blockIdx.x * 128;
    if (j0 > i0) return;   // entire 128x128 block above diagonal
    const int b = bh >> 4, h = bh & 15;
    const float* Qh = Q + (size_t)b * L_ * E_ + h * D_;
    const float* Kh = Kb + (size_t)b * L_ * E_ + h * D_;
    float* Sh = S + (size_t)bh * L_ * L_;

    __shared__ __align__(16) float As[16][128];
    __shared__ __align__(16) float Bs[16][128];
    const int tid = threadIdx.x;
    const int ty = tid >> 4, tx = tid & 15;
    const int lrow = tid >> 2, lq = tid & 3;

    float acc[8][8];
    #pragma unroll
    for (int i = 0; i < 8; i++)
        #pragma unroll
        for (int j = 0; j < 8; j++) acc[i][j] = 0.f;

    for (int k0 = 0; k0 < D_; k0 += 16) {
        #pragma unroll
        for (int it = 0; it < 2; ++it) {
            int r = lrow + it * 64;
            float4 av = *(const float4*)(Qh + (size_t)(i0 + r) * E_ + k0 + lq * 4);
            As[lq*4+0][r] = av.x; As[lq*4+1][r] = av.y;
            As[lq*4+2][r] = av.z; As[lq*4+3][r] = av.w;
            float4 bv = *(const float4*)(Kh + (size_t)(j0 + r) * E_ + k0 + lq * 4);
            Bs[lq*4+0][r] = bv.x; Bs[lq*4+1][r] = bv.y;
            Bs[lq*4+2][r] = bv.z; Bs[lq*4+3][r] = bv.w;
        }
        __syncthreads();
        #pragma unroll
        for (int kk = 0; kk < 16; ++kk) {
            float4 a0 = *(const float4*)&As[kk][ty*4];
            float4 a1 = *(const float4*)&As[kk][64 + ty*4];
            float4 b0 = *(const float4*)&Bs[kk][tx*4];
            float4 b1 = *(const float4*)&Bs[kk][64 + tx*4];
            float a[8] = {a0.x,a0.y,a0.z,a0.w,a1.x,a1.y,a1.z,a1.w};
            float b[8] = {b0.x,b0.y,b0.z,b0.w,b1.x,b1.y,b1.z,b1.w};
            #pragma unroll
            for (int i = 0; i < 8; i++)
                #pragma unroll
                for (int j = 0; j < 8; j++)
                    acc[i][j] = fmaf(a[i], b[j], acc[i][j]);
        }
        __syncthreads();
    }
    #pragma unroll
    for (int ih = 0; ih < 2; ih++)
        #pragma unroll
        for (int ii = 0; ii < 4; ii++) {
            int m = i0 + ih*64 + ty*4 + ii;
            #pragma unroll
            for (int jh = 0; jh < 2; jh++) {
                int n = j0 + jh*64 + tx*4;
                float4 o;
                o.x = acc[ih*4+ii][jh*4+0] * SCALE_;
                o.y = acc[ih*4+ii][jh*4+1] * SCALE_;
                o.z = acc[ih*4+ii][jh*4+2] * SCALE_;
                o.w = acc[ih*4+ii][jh*4+3] * SCALE_;
                *(float4*)(Sh + (size_t)m * L_ + n) = o;
            }
        }
}

// ============================================================================
// Causal softmax per row (in place). Reads j<=i only; writes full row
// (zeros for j>i) so PV can run block-dense. One 256-thread CTA per row.
// ============================================================================
__global__ __launch_bounds__(256) void softmax_kernel(float* __restrict__ S)
{
    const int row = blockIdx.x;            // bh*L + i
    const int i = row & (L_ - 1);
    const int n = i + 1;
    float* Sr = S + (size_t)row * L_;
    const int tid = threadIdx.x;
    const int lane = tid & 31, wid = tid >> 5;
    __shared__ float red[8];

    float pm = -3.0e38f;
    for (int j = tid; j < n; j += 256) pm = fmaxf(pm, Sr[j]);
    #pragma unroll
    for (int o = 16; o; o >>= 1) pm = fmaxf(pm, __shfl_xor_sync(0xffffffffu, pm, o));
    if (lane == 0) red[wid] = pm;
    __syncthreads();
    if (tid == 0) {
        float m = red[0];
        #pragma unroll
        for (int k = 1; k < 8; k++) m = fmaxf(m, red[k]);
        red[0] = m;
    }
    __syncthreads();
    const float m = red[0];
    __syncthreads();

    float e[4];
    int c = 0;
    float ps = 0.f;
    for (int j = tid; j < n; j += 256) {
        float v = __expf(Sr[j] - m);
        e[c++] = v;
        ps += v;
    }
    #pragma unroll
    for (int o = 16; o; o >>= 1) ps += __shfl_xor_sync(0xffffffffu, ps, o);
    if (lane == 0) red[wid] = ps;
    __syncthreads();
    if (tid == 0) {
        float s = 0.f;
        #pragma unroll
        for (int k = 0; k < 8; k++) s += red[k];
        red[0] = s;
    }
    __syncthreads();
    const float inv = 1.0f / red[0];

    c = 0;
    for (int j = tid; j < n; j += 256) Sr[j] = e[c++] * inv;
    for (int j = tid; j < L_; j += 256)
        if (j >= n) Sr[j] = 0.f;
}

// ============================================================================
// Batched PV: O_h[i,dd] = sum_j P[i,j] * V_h[j,dd]. K-loop truncated at the
// diagonal block (P zero above). P: [L,L] contiguous; V rows stride E.
// BM=128, BN=128 (=D), BK=16.
// ============================================================================
__global__ __launch_bounds__(256) void pv_kernel(
    const float* __restrict__ P, const float* __restrict__ V,
    float* __restrict__ O)
{
    const int bh = blockIdx.z;
    const int b = bh >> 4, h = bh & 15;
    const int i0 = blockIdx.y * 128;
    const float* Ph = P + (size_t)bh * L_ * L_;
    const float* Vh = V + (size_t)b * L_ * E_ + h * D_;
    float* Oh = O + (size_t)b * L_ * E_ + h * D_;

    __shared__ __align__(16) float As[16][128];
    __shared__ __align__(16) float Bs[16][128];
    const int tid = threadIdx.x;
    const int ty = tid >> 4, tx = tid & 15;
    const int lrow = tid >> 2, lq = tid & 3;
    const int kk0 = tid >> 5, q = tid & 31;   // for B-tile loads
    const int Keff = i0 + 128;                // causal truncation

    float acc[8][8];
    #pragma unroll
    for (int i = 0; i < 8; i++)
        #pragma unroll
        for (int j = 0; j < 8; j++) acc[i][j] = 0.f;

    for (int k0 = 0; k0 < Keff; k0 += 16) {
        #pragma unroll
        for (int it = 0; it < 2; ++it) {
            int r = lrow + it * 64;
            float4 av = *(const float4*)(Ph + (size_t)(i0 + r) * L_ + k0 + lq * 4);
            As[lq*4+0][r] = av.x; As[lq*4+1][r] = av.y;
            As[lq*4+2][r] = av.z; As[lq*4+3][r] = av.w;
        }
        #pragma unroll
        for (int it = 0; it < 2; ++it) {
            int kr = kk0 + it * 8;
            float4 bv = *(const float4*)(Vh + (size_t)(k0 + kr) * E_ + q * 4);
            *(float4*)&Bs[kr][q * 4] = bv;
        }
        __syncthreads();
        #pragma unroll
        for (int kk = 0; kk < 16; ++kk) {
            float4 a0 = *(const float4*)&As[kk][ty*4];
            float4 a1 = *(const float4*)&As[kk][64 + ty*4];
            float4 b0 = *(const float4*)&Bs[kk][tx*4];
            float4 b1 = *(const float4*)&Bs[kk][64 + tx*4];
            float a[8] = {a0.x,a0.y,a0.z,a0.w,a1.x,a1.y,a1.z,a1.w};
            float b[8] = {b0.x,b0.y,b0.z,b0.w,b1.x,b1.y,b1.z,b1.w};
            #pragma unroll
            for (int i = 0; i < 8; i++)
                #pragma unroll
                for (int j = 0; j < 8; j++)
                    acc[i][j] = fmaf(a[i], b[j], acc[i][j]);
        }
        __syncthreads();
    }
    #pragma unroll
    for (int ih = 0; ih < 2; ih++)
        #pragma unroll
        for (int ii = 0; ii < 4; ii++) {
            int m = i0 + ih*64 + ty*4 + ii;
            #pragma unroll
            for (int jh = 0; jh < 2; jh++) {
                int n = jh*64 + tx*4;
                float4 o;
                o.x = acc[ih*4+ii][jh*4+0];
                o.y = acc[ih*4+ii][jh*4+1];
                o.z = acc[ih*4+ii][jh*4+2];
                o.w = acc[ih*4+ii][jh*4+3];
                *(float4*)(Oh + (size_t)m * E_ + n) = o;
            }
        }
}

// ============================================================================
// v-orthogonalization: vn = v/max(||v||,eps); o -= (o.vn)*vn.
// One warp per (b,l,h). In-place on O.
// ============================================================================
__global__ __launch_bounds__(256) void ortho_kernel(
    float* __restrict__ O, const float* __restrict__ V)
{
    int gw = blockIdx.x * 8 + (threadIdx.x >> 5);
    int lane = threadIdx.x & 31;
    int row = gw / H_;
    int h = gw % H_;
    float* o = O + (size_t)row * E_ + h * D_;
    const float* v = V + (size_t)row * E_ + h * D_;

    float ov[4], vv[4];
    #pragma unroll
    for (int k = 0; k < 4; k++) { ov[k] = o[lane + 32*k]; vv[k] = v[lane + 32*k]; }
    float ss = 0.f, sv = 0.f;
    #pragma unroll
    for (int k = 0; k < 4; k++) { ss = fmaf(vv[k], vv[k], ss); sv = fmaf(ov[k], vv[k], sv); }
    #pragma unroll
    for (int off = 16; off; off >>= 1) {
        ss += __shfl_xor_sync(0xffffffffu, ss, off);
        sv += __shfl_xor_sync(0xffffffffu, sv, off);
    }
    float vnorm = sqrtf(ss);
    float inv = 1.0f / fmaxf(vnorm, 1e-9f);
    float coef = sv * inv * inv;     // (o.vn) * (1/||v||) applied to v
    #pragma unroll
    for (int k = 0; k < 4; k++) o[lane + 32*k] = ov[k] - coef * vv[k];
}

// ============================================================================
extern "C" void kernel_launch(void* const* d_in, const int* in_sizes, int n_in,
                              void* d_out, int out_size)
{
    const float* query = (const float*)d_in[0];
    const float* key   = (const float*)d_in[1];
    const float* value = (const float*)d_in[2];
    /* d_in[3] attn_mask: causal tril, hard-coded */
    const float* cosp  = (const float*)d_in[4];
    const float* sinp  = (const float*)d_in[5];
    const float* Wq = (const float*)d_in[6];
    const float* bq = (const float*)d_in[7];
    const float* Wk = (const float*)d_in[8];
    const float* bk = (const float*)d_in[9];
    const float* Wv = (const float*)d_in[10];
    const float* bv = (const float*)d_in[11];
    const float* Wo = (const float*)d_in[12];
    const float* bo = (const float*)d_in[13];
    float* out = (float*)d_out;

    float *gQ, *gK, *gV, *gO, *gS;
    cudaGetSymbolAddress((void**)&gQ, g_Q);
    cudaGetSymbolAddress((void**)&gK, g_K);
    cudaGetSymbolAddress((void**)&gV, g_V);
    cudaGetSymbolAddress((void**)&gO, g_O);
    cudaGetSymbolAddress((void**)&gS, g_S);

    const dim3 blk(256);
    const dim3 gProj(E_ / 128, BL_ / 128);             // 16 x 32

    gemm_nt_bias<<<gProj, blk>>>(query, Wq, bq, gQ, BL_, E_, E_);
    gemm_nt_bias<<<gProj, blk>>>(key,   Wk, bk, gK, BL_, E_, E_);
    gemm_nt_bias<<<gProj, blk>>>(value, Wv, bv, gV, BL_, E_, E_);

    normrope_kernel<<<(2 * BL_ * H_) / 8, blk>>>(gQ, gK, cosp, sinp);

    scores_kernel<<<dim3(L_ / 128, L_ / 128, BH_), blk>>>(gQ, gK, gS);

    softmax_kernel<<<BH_ * L_, blk>>>(gS);

    pv_kernel<<<dim3(1, L_ / 128, BH_), blk>>>(gS, gV, gO);

    ortho_kernel<<<(BL_ * H_) / 8, blk>>>(gO, gV);

    gemm_nt_bias<<<gProj, blk>>>(gO, Wo, bo, out, BL_, E_, E_);
}

// round 7
// speedup vs baseline: 1.8907x; 1.8907x over previous
#include <cuda_runtime.h>
#include <cuda_bf16.h>
#include <cstdint>
#include <math.h>

typedef unsigned int u32;
typedef unsigned long long u64;

// Problem constants
#define B_  4
#define L_  1024
#define E_  2048
#define H_  16
#define D_  128
#define BL_ (B_*L_)            // 4096
#define BH_ (B_*H_)            // 64
#define SCALE_ 0.08838834764831845f   // 1/sqrt(128)

// -------- scratch (device globals; no allocation allowed) --------
__device__ float g_Q[(u64)BL_*E_];
__device__ float g_K[(u64)BL_*E_];
__device__ float g_V[(u64)BL_*E_];
__device__ float g_O[(u64)BL_*E_];
__device__ float g_S[(u64)BH_*L_*L_];           // 256MB scores/probs
__device__ __nv_bfloat16 g_Ahi[(u64)BL_*E_];    // activation split (16MB)
__device__ __nv_bfloat16 g_Alo[(u64)BL_*E_];
__device__ __nv_bfloat16 g_Whi[(u64)E_*E_];     // weight split (8MB)
__device__ __nv_bfloat16 g_Wlo[(u64)E_*E_];

// ============================================================================
// helpers
// ============================================================================
__device__ __forceinline__ void cp16(u32 dst, const void* src) {
    asm volatile("cp.async.cg.shared.global [%0], [%1], 16;" :: "r"(dst), "l"(src) : "memory");
}

// m16n8k16 bf16 MMA, fp32 accumulate in place
__device__ __forceinline__ void mma_bf16(float* d, const u32* a, const u32* b) {
    asm volatile(
        "mma.sync.aligned.m16n8k16.row.col.f32.bf16.bf16.f32 "
        "{%0,%1,%2,%3}, {%4,%5,%6,%7}, {%8,%9}, {%0,%1,%2,%3};"
        : "+f"(d[0]), "+f"(d[1]), "+f"(d[2]), "+f"(d[3])
        : "r"(a[0]), "r"(a[1]), "r"(a[2]), "r"(a[3]), "r"(b[0]), "r"(b[1]));
}

// ============================================================================
// Split fp32 -> bf16 hi + bf16 lo  (x = hi + lo up to ~2^-18 relative)
// ============================================================================
__global__ __launch_bounds__(256) void split_kernel(
    const float* __restrict__ X, __nv_bfloat16* __restrict__ hi,
    __nv_bfloat16* __restrict__ lo, int n)
{
    int i = (blockIdx.x * 256 + threadIdx.x) * 4;
    if (i >= n) return;
    float4 x = *(const float4*)(X + i);
    float v[4] = {x.x, x.y, x.z, x.w};
    unsigned short hv[4], lv[4];
    #pragma unroll
    for (int k = 0; k < 4; k++) {
        __nv_bfloat16 h = __float2bfloat16(v[k]);
        __nv_bfloat16 l = __float2bfloat16(v[k] - __bfloat162float(h));
        hv[k] = __bfloat16_as_ushort(h);
        lv[k] = __bfloat16_as_ushort(l);
    }
    *(ushort4*)(hi + i) = make_ushort4(hv[0], hv[1], hv[2], hv[3]);
    *(ushort4*)(lo + i) = make_ushort4(lv[0], lv[1], lv[2], lv[3]);
}

// ============================================================================
// mma.sync GEMM: C[4096,2048] = A @ B^T + bias, bf16 hi/lo 3-product split.
// CTA tile 128x128, 8 warps (4m x 2n), warp tile 32x64, BK=32,
// cp.async double buffer. SMEM rows padded to 40 halves (conflict-free).
// ============================================================================
#define GM_M 4096
#define GM_N 2048
#define GM_K 2048
#define BKH 32                 // K-chunk (halves)
#define ROWP 40                // padded row stride (halves)
#define T_ALO_H 5120           // 128*40
#define T_BHI_H 10240
#define T_BLO_H 15360
#define STAGEH 20480           // halves per stage
#define NCH (GM_K / BKH)       // 64
#define SMEM_GEMM_BYTES (2 * STAGEH * 2)   // 81920

__device__ __forceinline__ void g_load_stage(
    u32 sbase, int s, int m0, int n0, int k0, int tid,
    const __nv_bfloat16* __restrict__ Ahi, const __nv_bfloat16* __restrict__ Alo,
    const __nv_bfloat16* __restrict__ Bhi, const __nv_bfloat16* __restrict__ Blo)
{
    u32 st = sbase + (u32)s * (STAGEH * 2);
    #pragma unroll
    for (int i = 0; i < 2; ++i) {
        int id = tid + i * 256;          // 512 ids: 128 rows x 4 segs
        int r = id >> 2, sg = id & 3;
        u32 doff = (u32)(r * ROWP + sg * 8) * 2;
        u64 ao = (u64)(m0 + r) * GM_K + k0 + sg * 8;
        u64 bo = (u64)(n0 + r) * GM_K + k0 + sg * 8;
        cp16(st + doff, Ahi + ao);
        cp16(st + T_ALO_H * 2 + doff, Alo + ao);
        cp16(st + T_BHI_H * 2 + doff, Bhi + bo);
        cp16(st + T_BLO_H * 2 + doff, Blo + bo);
    }
    asm volatile("cp.async.commit_group;" ::: "memory");
}

__global__ __launch_bounds__(256) void gemm_mma_kernel(
    const __nv_bfloat16* __restrict__ Ahi, const __nv_bfloat16* __restrict__ Alo,
    const __nv_bfloat16* __restrict__ Bhi, const __nv_bfloat16* __restrict__ Blo,
    const float* __restrict__ bias, float* __restrict__ C)
{
    extern __shared__ __align__(16) __nv_bfloat16 sh[];
    const int tid = threadIdx.x;
    const int m0 = blockIdx.y * 128;
    const int n0 = blockIdx.x * 128;
    const int warp = tid >> 5, lane = tid & 31;
    const int wm = warp & 3, wn = warp >> 2;          // 4 m-warps x 2 n-warps
    const u32 sbase = (u32)__cvta_generic_to_shared(sh);

    float acc[2][8][4];
    #pragma unroll
    for (int i = 0; i < 2; i++)
        #pragma unroll
        for (int j = 0; j < 8; j++)
            #pragma unroll
            for (int k = 0; k < 4; k++) acc[i][j][k] = 0.f;

    g_load_stage(sbase, 0, m0, n0, 0,   tid, Ahi, Alo, Bhi, Blo);
    g_load_stage(sbase, 1, m0, n0, BKH, tid, Ahi, Alo, Bhi, Blo);

    const int fr = lane >> 2;            // fragment row / n-index
    const int fc = (lane & 3) * 2;       // fragment k-offset

    for (int c = 0; c < NCH; ++c) {
        const int s = c & 1;
        if (c < NCH - 1) asm volatile("cp.async.wait_group 1;" ::: "memory");
        else             asm volatile("cp.async.wait_group 0;" ::: "memory");
        __syncthreads();

        const __nv_bfloat16* sS = sh + s * STAGEH;
        const __nv_bfloat16* aH = sS + (wm * 32 + fr) * ROWP + fc;
        const __nv_bfloat16* aL = aH + T_ALO_H;
        const __nv_bfloat16* bH = sS + T_BHI_H + (wn * 64 + fr) * ROWP + fc;
        const __nv_bfloat16* bL = bH + (T_BLO_H - T_BHI_H);

        #pragma unroll
        for (int kk = 0; kk < BKH; kk += 16) {
            u32 fah[2][4], fal[2][4];
            #pragma unroll
            for (int mt = 0; mt < 2; ++mt) {
                const __nv_bfloat16* p = aH + mt * 16 * ROWP + kk;
                fah[mt][0] = *(const u32*)(p);
                fah[mt][1] = *(const u32*)(p + 8 * ROWP);
                fah[mt][2] = *(const u32*)(p + 8);
                fah[mt][3] = *(const u32*)(p + 8 * ROWP + 8);
                const __nv_bfloat16* q = aL + mt * 16 * ROWP + kk;
                fal[mt][0] = *(const u32*)(q);
                fal[mt][1] = *(const u32*)(q + 8 * ROWP);
                fal[mt][2] = *(const u32*)(q + 8);
                fal[mt][3] = *(const u32*)(q + 8 * ROWP + 8);
            }
            #pragma unroll
            for (int nt = 0; nt < 8; ++nt) {
                u32 fbh[2], fbl[2];
                const __nv_bfloat16* p = bH + nt * 8 * ROWP + kk;
                fbh[0] = *(const u32*)(p);
                fbh[1] = *(const u32*)(p + 8);
                const __nv_bfloat16* q = bL + nt * 8 * ROWP + kk;
                fbl[0] = *(const u32*)(q);
                fbl[1] = *(const u32*)(q + 8);
                #pragma unroll
                for (int mt = 0; mt < 2; ++mt) {
                    mma_bf16(acc[mt][nt], fah[mt], fbh);
                    mma_bf16(acc[mt][nt], fah[mt], fbl);
                    mma_bf16(acc[mt][nt], fal[mt], fbh);
                }
            }
        }
        __syncthreads();
        if (c + 2 < NCH)
            g_load_stage(sbase, s, m0, n0, (c + 2) * BKH, tid, Ahi, Alo, Bhi, Blo);
    }

    // epilogue
    #pragma unroll
    for (int mt = 0; mt < 2; ++mt) {
        #pragma unroll
        for (int nt = 0; nt < 8; ++nt) {
            int m = m0 + wm * 32 + mt * 16 + fr;
            int n = n0 + wn * 64 + nt * 8 + fc;
            float b0 = bias[n], b1 = bias[n + 1];
            float2 v0 = make_float2(acc[mt][nt][0] + b0, acc[mt][nt][1] + b1);
            float2 v1 = make_float2(acc[mt][nt][2] + b0, acc[mt][nt][3] + b1);
            *(float2*)(C + (u64)m * GM_N + n) = v0;
            *(float2*)(C + (u64)(m + 8) * GM_N + n) = v1;
        }
    }
}

// ============================================================================
// Fused RMSNorm + rotary for Q and K. One warp per (b,l,h) head-vector.
// ============================================================================
__global__ __launch_bounds__(256) void normrope_kernel(
    float* __restrict__ Q, float* __restrict__ Kb,
    const float* __restrict__ cosp, const float* __restrict__ sinp)
{
    int gw = blockIdx.x * 8 + (threadIdx.x >> 5);
    int lane = threadIdx.x & 31;
    float* X = (gw < BL_ * H_) ? Q : Kb;
    int w = gw % (BL_ * H_);
    int row = w / H_;
    int h   = w % H_;
    int i   = row & (L_ - 1);
    float* x = X + (u64)row * E_ + h * D_;

    float v0 = x[lane], v1 = x[lane+32], v2 = x[lane+64], v3 = x[lane+96];
    float ss = v0*v0 + v1*v1 + v2*v2 + v3*v3;
    #pragma unroll
    for (int o = 16; o; o >>= 1) ss += __shfl_xor_sync(0xffffffffu, ss, o);
    float r = rsqrtf(ss * (1.0f / 128.0f) + 1e-6f);
    v0 *= r; v1 *= r; v2 *= r; v3 *= r;

    float c0 = cosp[i*64 + lane],      s0 = sinp[i*64 + lane];
    float c1 = cosp[i*64 + lane + 32], s1 = sinp[i*64 + lane + 32];
    x[lane]      = v0 * c0 - v2 * s0;
    x[lane + 64] = v0 * s0 + v2 * c0;
    x[lane + 32] = v1 * c1 - v3 * s1;
    x[lane + 96] = v1 * s1 + v3 * c1;
}

// ============================================================================
// Batched causal scores (fp32 SIMT)
// ============================================================================
__global__ __launch_bounds__(256) void scores_kernel(
    const float* __restrict__ Q, const float* __restrict__ Kb,
    float* __restrict__ S)
{
    const int bh = blockIdx.z;
    const int i0 = blockIdx.y * 128;
    const int j0 = blockIdx.x * 128;
    if (j0 > i0) return;
    const int b = bh >> 4, h = bh & 15;
    const float* Qh = Q + (u64)b * L_ * E_ + h * D_;
    const float* Kh = Kb + (u64)b * L_ * E_ + h * D_;
    float* Sh = S + (u64)bh * L_ * L_;

    __shared__ __align__(16) float As[16][128];
    __shared__ __align__(16) float Bs[16][128];
    const int tid = threadIdx.x;
    const int ty = tid >> 4, tx = tid & 15;
    const int lrow = tid >> 2, lq = tid & 3;

    float acc[8][8];
    #pragma unroll
    for (int i = 0; i < 8; i++)
        #pragma unroll
        for (int j = 0; j < 8; j++) acc[i][j] = 0.f;

    for (int k0 = 0; k0 < D_; k0 += 16) {
        #pragma unroll
        for (int it = 0; it < 2; ++it) {
            int r = lrow + it * 64;
            float4 av = *(const float4*)(Qh + (u64)(i0 + r) * E_ + k0 + lq * 4);
            As[lq*4+0][r] = av.x; As[lq*4+1][r] = av.y;
            As[lq*4+2][r] = av.z; As[lq*4+3][r] = av.w;
            float4 bv = *(const float4*)(Kh + (u64)(j0 + r) * E_ + k0 + lq * 4);
            Bs[lq*4+0][r] = bv.x; Bs[lq*4+1][r] = bv.y;
            Bs[lq*4+2][r] = bv.z; Bs[lq*4+3][r] = bv.w;
        }
        __syncthreads();
        #pragma unroll
        for (int kk = 0; kk < 16; ++kk) {
            float4 a0 = *(const float4*)&As[kk][ty*4];
            float4 a1 = *(const float4*)&As[kk][64 + ty*4];
            float4 b0 = *(const float4*)&Bs[kk][tx*4];
            float4 b1 = *(const float4*)&Bs[kk][64 + tx*4];
            float a[8] = {a0.x,a0.y,a0.z,a0.w,a1.x,a1.y,a1.z,a1.w};
            float b[8] = {b0.x,b0.y,b0.z,b0.w,b1.x,b1.y,b1.z,b1.w};
            #pragma unroll
            for (int i = 0; i < 8; i++)
                #pragma unroll
                for (int j = 0; j < 8; j++)
                    acc[i][j] = fmaf(a[i], b[j], acc[i][j]);
        }
        __syncthreads();
    }
    #pragma unroll
    for (int ih = 0; ih < 2; ih++)
        #pragma unroll
        for (int ii = 0; ii < 4; ii++) {
            int m = i0 + ih*64 + ty*4 + ii;
            #pragma unroll
            for (int jh = 0; jh < 2; jh++) {
                int n = j0 + jh*64 + tx*4;
                float4 o;
                o.x = acc[ih*4+ii][jh*4+0] * SCALE_;
                o.y = acc[ih*4+ii][jh*4+1] * SCALE_;
                o.z = acc[ih*4+ii][jh*4+2] * SCALE_;
                o.w = acc[ih*4+ii][jh*4+3] * SCALE_;
                *(float4*)(Sh + (u64)m * L_ + n) = o;
            }
        }
}

// ============================================================================
// Causal softmax per row (in place)
// ============================================================================
__global__ __launch_bounds__(256) void softmax_kernel(float* __restrict__ S)
{
    const int row = blockIdx.x;
    const int i = row & (L_ - 1);
    const int n = i + 1;
    float* Sr = S + (u64)row * L_;
    const int tid = threadIdx.x;
    const int lane = tid & 31, wid = tid >> 5;
    __shared__ float red[8];

    float pm = -3.0e38f;
    for (int j = tid; j < n; j += 256) pm = fmaxf(pm, Sr[j]);
    #pragma unroll
    for (int o = 16; o; o >>= 1) pm = fmaxf(pm, __shfl_xor_sync(0xffffffffu, pm, o));
    if (lane == 0) red[wid] = pm;
    __syncthreads();
    if (tid == 0) {
        float m = red[0];
        #pragma unroll
        for (int k = 1; k < 8; k++) m = fmaxf(m, red[k]);
        red[0] = m;
    }
    __syncthreads();
    const float m = red[0];
    __syncthreads();

    float e[4];
    int c = 0;
    float ps = 0.f;
    for (int j = tid; j < n; j += 256) {
        float v = __expf(Sr[j] - m);
        e[c++] = v;
        ps += v;
    }
    #pragma unroll
    for (int o = 16; o; o >>= 1) ps += __shfl_xor_sync(0xffffffffu, ps, o);
    if (lane == 0) red[wid] = ps;
    __syncthreads();
    if (tid == 0) {
        float s = 0.f;
        #pragma unroll
        for (int k = 0; k < 8; k++) s += red[k];
        red[0] = s;
    }
    __syncthreads();
    const float inv = 1.0f / red[0];

    c = 0;
    for (int j = tid; j < n; j += 256) Sr[j] = e[c++] * inv;
    for (int j = tid; j < L_; j += 256)
        if (j >= n) Sr[j] = 0.f;
}

// ============================================================================
// Batched PV (fp32 SIMT, causal-truncated K loop)
// ============================================================================
__global__ __launch_bounds__(256) void pv_kernel(
    const float* __restrict__ P, const float* __restrict__ V,
    float* __restrict__ O)
{
    const int bh = blockIdx.z;
    const int b = bh >> 4, h = bh & 15;
    const int i0 = blockIdx.y * 128;
    const float* Ph = P + (u64)bh * L_ * L_;
    const float* Vh = V + (u64)b * L_ * E_ + h * D_;
    float* Oh = O + (u64)b * L_ * E_ + h * D_;

    __shared__ __align__(16) float As[16][128];
    __shared__ __align__(16) float Bs[16][128];
    const int tid = threadIdx.x;
    const int ty = tid >> 4, tx = tid & 15;
    const int lrow = tid >> 2, lq = tid & 3;
    const int kk0 = tid >> 5, q = tid & 31;
    const int Keff = i0 + 128;

    float acc[8][8];
    #pragma unroll
    for (int i = 0; i < 8; i++)
        #pragma unroll
        for (int j = 0; j < 8; j++) acc[i][j] = 0.f;

    for (int k0 = 0; k0 < Keff; k0 += 16) {
        #pragma unroll
        for (int it = 0; it < 2; ++it) {
            int r = lrow + it * 64;
            float4 av = *(const float4*)(Ph + (u64)(i0 + r) * L_ + k0 + lq * 4);
            As[lq*4+0][r] = av.x; As[lq*4+1][r] = av.y;
            As[lq*4+2][r] = av.z; As[lq*4+3][r] = av.w;
        }
        #pragma unroll
        for (int it = 0; it < 2; ++it) {
            int kr = kk0 + it * 8;
            float4 bv = *(const float4*)(Vh + (u64)(k0 + kr) * E_ + q * 4);
            *(float4*)&Bs[kr][q * 4] = bv;
        }
        __syncthreads();
        #pragma unroll
        for (int kk = 0; kk < 16; ++kk) {
            float4 a0 = *(const float4*)&As[kk][ty*4];
            float4 a1 = *(const float4*)&As[kk][64 + ty*4];
            float4 b0 = *(const float4*)&Bs[kk][tx*4];
            float4 b1 = *(const float4*)&Bs[kk][64 + tx*4];
            float a[8] = {a0.x,a0.y,a0.z,a0.w,a1.x,a1.y,a1.z,a1.w};
            float b[8] = {b0.x,b0.y,b0.z,b0.w,b1.x,b1.y,b1.z,b1.w};
            #pragma unroll
            for (int i = 0; i < 8; i++)
                #pragma unroll
                for (int j = 0; j < 8; j++)
                    acc[i][j] = fmaf(a[i], b[j], acc[i][j]);
        }
        __syncthreads();
    }
    #pragma unroll
    for (int ih = 0; ih < 2; ih++)
        #pragma unroll
        for (int ii = 0; ii < 4; ii++) {
            int m = i0 + ih*64 + ty*4 + ii;
            #pragma unroll
            for (int jh = 0; jh < 2; jh++) {
                int n = jh*64 + tx*4;
                float4 o;
                o.x = acc[ih*4+ii][jh*4+0];
                o.y = acc[ih*4+ii][jh*4+1];
                o.z = acc[ih*4+ii][jh*4+2];
                o.w = acc[ih*4+ii][jh*4+3];
                *(float4*)(Oh + (u64)m * E_ + n) = o;
            }
        }
}

// ============================================================================
// v-orthogonalization
// ============================================================================
__global__ __launch_bounds__(256) void ortho_kernel(
    float* __restrict__ O, const float* __restrict__ V)
{
    int gw = blockIdx.x * 8 + (threadIdx.x >> 5);
    int lane = threadIdx.x & 31;
    int row = gw / H_;
    int h = gw % H_;
    float* o = O + (u64)row * E_ + h * D_;
    const float* v = V + (u64)row * E_ + h * D_;

    float ov[4], vv[4];
    #pragma unroll
    for (int k = 0; k < 4; k++) { ov[k] = o[lane + 32*k]; vv[k] = v[lane + 32*k]; }
    float ss = 0.f, sv = 0.f;
    #pragma unroll
    for (int k = 0; k < 4; k++) { ss = fmaf(vv[k], vv[k], ss); sv = fmaf(ov[k], vv[k], sv); }
    #pragma unroll
    for (int off = 16; off; off >>= 1) {
        ss += __shfl_xor_sync(0xffffffffu, ss, off);
        sv += __shfl_xor_sync(0xffffffffu, sv, off);
    }
    float vnorm = sqrtf(ss);
    float inv = 1.0f / fmaxf(vnorm, 1e-9f);
    float coef = sv * inv * inv;
    #pragma unroll
    for (int k = 0; k < 4; k++) o[lane + 32*k] = ov[k] - coef * vv[k];
}

// ============================================================================
extern "C" void kernel_launch(void* const* d_in, const int* in_sizes, int n_in,
                              void* d_out, int out_size)
{
    const float* query = (const float*)d_in[0];
    const float* key   = (const float*)d_in[1];
    const float* value = (const float*)d_in[2];
    /* d_in[3] attn_mask: causal tril, hard-coded */
    const float* cosp  = (const float*)d_in[4];
    const float* sinp  = (const float*)d_in[5];
    const float* Wq = (const float*)d_in[6];
    const float* bq = (const float*)d_in[7];
    const float* Wk = (const float*)d_in[8];
    const float* bk = (const float*)d_in[9];
    const float* Wv = (const float*)d_in[10];
    const float* bv = (const float*)d_in[11];
    const float* Wo = (const float*)d_in[12];
    const float* bo = (const float*)d_in[13];
    float* out = (float*)d_out;

    float *gQ, *gK, *gV, *gO, *gS;
    __nv_bfloat16 *gAhi, *gAlo, *gWhi, *gWlo;
    cudaGetSymbolAddress((void**)&gQ, g_Q);
    cudaGetSymbolAddress((void**)&gK, g_K);
    cudaGetSymbolAddress((void**)&gV, g_V);
    cudaGetSymbolAddress((void**)&gO, g_O);
    cudaGetSymbolAddress((void**)&gS, g_S);
    cudaGetSymbolAddress((void**)&gAhi, g_Ahi);
    cudaGetSymbolAddress((void**)&gAlo, g_Alo);
    cudaGetSymbolAddress((void**)&gWhi, g_Whi);
    cudaGetSymbolAddress((void**)&gWlo, g_Wlo);

    cudaFuncSetAttribute(gemm_mma_kernel, cudaFuncAttributeMaxDynamicSharedMemorySize,
                         SMEM_GEMM_BYTES);

    const dim3 blk(256);
    const int nAct = BL_ * E_;   // 8388608
    const int nW   = E_ * E_;    // 4194304
    const dim3 gGemm(GM_N / 128, GM_M / 128);   // (16, 32)

    // Q projection
    split_kernel<<<nAct / 1024, blk>>>(query, gAhi, gAlo, nAct);
    split_kernel<<<nW / 1024, blk>>>(Wq, gWhi, gWlo, nW);
    gemm_mma_kernel<<<gGemm, blk, SMEM_GEMM_BYTES>>>(gAhi, gAlo, gWhi, gWlo, bq, gQ);
    // K projection
    split_kernel<<<nAct / 1024, blk>>>(key, gAhi, gAlo, nAct);
    split_kernel<<<nW / 1024, blk>>>(Wk, gWhi, gWlo, nW);
    gemm_mma_kernel<<<gGemm, blk, SMEM_GEMM_BYTES>>>(gAhi, gAlo, gWhi, gWlo, bk, gK);
    // V projection
    split_kernel<<<nAct / 1024, blk>>>(value, gAhi, gAlo, nAct);
    split_kernel<<<nW / 1024, blk>>>(Wv, gWhi, gWlo, nW);
    gemm_mma_kernel<<<gGemm, blk, SMEM_GEMM_BYTES>>>(gAhi, gAlo, gWhi, gWlo, bv, gV);

    normrope_kernel<<<(2 * BL_ * H_) / 8, blk>>>(gQ, gK, cosp, sinp);

    scores_kernel<<<dim3(L_ / 128, L_ / 128, BH_), blk>>>(gQ, gK, gS);
    softmax_kernel<<<BH_ * L_, blk>>>(gS);
    pv_kernel<<<dim3(1, L_ / 128, BH_), blk>>>(gS, gV, gO);
    ortho_kernel<<<(BL_ * H_) / 8, blk>>>(gO, gV);

    // Output projection
    split_kernel<<<nAct / 1024, blk>>>(gO, gAhi, gAlo, nAct);
    split_kernel<<<nW / 1024, blk>>>(Wo, gWhi, gWlo, nW);
    gemm_mma_kernel<<<gGemm, blk, SMEM_GEMM_BYTES>>>(gAhi, gAlo, gWhi, gWlo, bo, out);
}

// round 8
// speedup vs baseline: 2.1577x; 1.1412x over previous
#include <cuda_runtime.h>
#include <cuda_bf16.h>
#include <cstdint>
#include <math.h>

typedef unsigned int u32;
typedef unsigned long long u64;

// Problem constants
#define B_  4
#define L_  1024
#define E_  2048
#define H_  16
#define D_  128
#define BL_ (B_*L_)            // 4096
#define BH_ (B_*H_)            // 64
#define SCALE_ 0.08838834764831845f   // 1/sqrt(128)

// -------- scratch (device globals; no allocation allowed) --------
__device__ float g_Q[(u64)BL_*E_];
__device__ float g_K[(u64)BL_*E_];
__device__ float g_V[(u64)BL_*E_];
__device__ float g_O[(u64)BL_*E_];
__device__ float g_S[(u64)BH_*L_*L_];            // 256MB scores
__device__ __nv_bfloat16 g_Ahi[(u64)BL_*E_];     // activation split (16MB)
__device__ __nv_bfloat16 g_Alo[(u64)BL_*E_];
__device__ __nv_bfloat16 g_Whi[(u64)E_*E_];      // weight split (8MB)
__device__ __nv_bfloat16 g_Wlo[(u64)E_*E_];
__device__ __nv_bfloat16 g_Qhi[(u64)BH_*L_*D_];  // [bh][l][d] 16MB
__device__ __nv_bfloat16 g_Qlo[(u64)BH_*L_*D_];
__device__ __nv_bfloat16 g_Khi[(u64)BH_*L_*D_];
__device__ __nv_bfloat16 g_Klo[(u64)BH_*L_*D_];
__device__ __nv_bfloat16 g_Vthi[(u64)BH_*D_*L_]; // [bh][d][l] 16MB
__device__ __nv_bfloat16 g_Vtlo[(u64)BH_*D_*L_];
__device__ __nv_bfloat16 g_Phi[(u64)BH_*L_*L_];  // [bh][i][j] 128MB
__device__ __nv_bfloat16 g_Plo[(u64)BH_*L_*L_];

// ============================================================================
// helpers
// ============================================================================
__device__ __forceinline__ void cp16(u32 dst, const void* src) {
    asm volatile("cp.async.cg.shared.global [%0], [%1], 16;" :: "r"(dst), "l"(src) : "memory");
}

__device__ __forceinline__ void mma_bf16(float* d, const u32* a, const u32* b) {
    asm volatile(
        "mma.sync.aligned.m16n8k16.row.col.f32.bf16.bf16.f32 "
        "{%0,%1,%2,%3}, {%4,%5,%6,%7}, {%8,%9}, {%0,%1,%2,%3};"
        : "+f"(d[0]), "+f"(d[1]), "+f"(d[2]), "+f"(d[3])
        : "r"(a[0]), "r"(a[1]), "r"(a[2]), "r"(a[3]), "r"(b[0]), "r"(b[1]));
}

__device__ __forceinline__ void split1(float v, unsigned short& h, unsigned short& l) {
    __nv_bfloat16 hb = __float2bfloat16(v);
    __nv_bfloat16 lb = __float2bfloat16(v - __bfloat162float(hb));
    h = __bfloat16_as_ushort(hb);
    l = __bfloat16_as_ushort(lb);
}

// ============================================================================
// Split fp32 -> bf16 hi + bf16 lo
// ============================================================================
__global__ __launch_bounds__(256) void split_kernel(
    const float* __restrict__ X, __nv_bfloat16* __restrict__ hi,
    __nv_bfloat16* __restrict__ lo, int n)
{
    int i = (blockIdx.x * 256 + threadIdx.x) * 4;
    if (i >= n) return;
    float4 x = *(const float4*)(X + i);
    float v[4] = {x.x, x.y, x.z, x.w};
    unsigned short hv[4], lv[4];
    #pragma unroll
    for (int k = 0; k < 4; k++) split1(v[k], hv[k], lv[k]);
    *(ushort4*)(hi + i) = make_ushort4(hv[0], hv[1], hv[2], hv[3]);
    *(ushort4*)(lo + i) = make_ushort4(lv[0], lv[1], lv[2], lv[3]);
}

// ============================================================================
// Projection GEMM (unchanged from R7 WIN): C = A @ B^T + bias, hi/lo split
// ============================================================================
#define GM_M 4096
#define GM_N 2048
#define GM_K 2048
#define BKH 32
#define ROWP 40
#define T_ALO_H 5120
#define T_BHI_H 10240
#define T_BLO_H 15360
#define STAGEH 20480
#define NCH (GM_K / BKH)
#define SMEM_GEMM_BYTES (2 * STAGEH * 2)   // 81920

__device__ __forceinline__ void g_load_stage(
    u32 sbase, int s, int m0, int n0, int k0, int tid,
    const __nv_bfloat16* __restrict__ Ahi, const __nv_bfloat16* __restrict__ Alo,
    const __nv_bfloat16* __restrict__ Bhi, const __nv_bfloat16* __restrict__ Blo)
{
    u32 st = sbase + (u32)s * (STAGEH * 2);
    #pragma unroll
    for (int i = 0; i < 2; ++i) {
        int id = tid + i * 256;
        int r = id >> 2, sg = id & 3;
        u32 doff = (u32)(r * ROWP + sg * 8) * 2;
        u64 ao = (u64)(m0 + r) * GM_K + k0 + sg * 8;
        u64 bo = (u64)(n0 + r) * GM_K + k0 + sg * 8;
        cp16(st + doff, Ahi + ao);
        cp16(st + T_ALO_H * 2 + doff, Alo + ao);
        cp16(st + T_BHI_H * 2 + doff, Bhi + bo);
        cp16(st + T_BLO_H * 2 + doff, Blo + bo);
    }
    asm volatile("cp.async.commit_group;" ::: "memory");
}

__global__ __launch_bounds__(256) void gemm_mma_kernel(
    const __nv_bfloat16* __restrict__ Ahi, const __nv_bfloat16* __restrict__ Alo,
    const __nv_bfloat16* __restrict__ Bhi, const __nv_bfloat16* __restrict__ Blo,
    const float* __restrict__ bias, float* __restrict__ C)
{
    extern __shared__ __align__(16) __nv_bfloat16 sh[];
    const int tid = threadIdx.x;
    const int m0 = blockIdx.y * 128;
    const int n0 = blockIdx.x * 128;
    const int warp = tid >> 5, lane = tid & 31;
    const int wm = warp & 3, wn = warp >> 2;
    const u32 sbase = (u32)__cvta_generic_to_shared(sh);

    float acc[2][8][4];
    #pragma unroll
    for (int i = 0; i < 2; i++)
        #pragma unroll
        for (int j = 0; j < 8; j++)
            #pragma unroll
            for (int k = 0; k < 4; k++) acc[i][j][k] = 0.f;

    g_load_stage(sbase, 0, m0, n0, 0,   tid, Ahi, Alo, Bhi, Blo);
    g_load_stage(sbase, 1, m0, n0, BKH, tid, Ahi, Alo, Bhi, Blo);

    const int fr = lane >> 2;
    const int fc = (lane & 3) * 2;

    for (int c = 0; c < NCH; ++c) {
        const int s = c & 1;
        if (c < NCH - 1) asm volatile("cp.async.wait_group 1;" ::: "memory");
        else             asm volatile("cp.async.wait_group 0;" ::: "memory");
        __syncthreads();

        const __nv_bfloat16* sS = sh + s * STAGEH;
        const __nv_bfloat16* aH = sS + (wm * 32 + fr) * ROWP + fc;
        const __nv_bfloat16* aL = aH + T_ALO_H;
        const __nv_bfloat16* bH = sS + T_BHI_H + (wn * 64 + fr) * ROWP + fc;
        const __nv_bfloat16* bL = bH + (T_BLO_H - T_BHI_H);

        #pragma unroll
        for (int kk = 0; kk < BKH; kk += 16) {
            u32 fah[2][4], fal[2][4];
            #pragma unroll
            for (int mt = 0; mt < 2; ++mt) {
                const __nv_bfloat16* p = aH + mt * 16 * ROWP + kk;
                fah[mt][0] = *(const u32*)(p);
                fah[mt][1] = *(const u32*)(p + 8 * ROWP);
                fah[mt][2] = *(const u32*)(p + 8);
                fah[mt][3] = *(const u32*)(p + 8 * ROWP + 8);
                const __nv_bfloat16* q = aL + mt * 16 * ROWP + kk;
                fal[mt][0] = *(const u32*)(q);
                fal[mt][1] = *(const u32*)(q + 8 * ROWP);
                fal[mt][2] = *(const u32*)(q + 8);
                fal[mt][3] = *(const u32*)(q + 8 * ROWP + 8);
            }
            #pragma unroll
            for (int nt = 0; nt < 8; ++nt) {
                u32 fbh[2], fbl[2];
                const __nv_bfloat16* p = bH + nt * 8 * ROWP + kk;
                fbh[0] = *(const u32*)(p);
                fbh[1] = *(const u32*)(p + 8);
                const __nv_bfloat16* q = bL + nt * 8 * ROWP + kk;
                fbl[0] = *(const u32*)(q);
                fbl[1] = *(const u32*)(q + 8);
                #pragma unroll
                for (int mt = 0; mt < 2; ++mt) {
                    mma_bf16(acc[mt][nt], fah[mt], fbh);
                    mma_bf16(acc[mt][nt], fah[mt], fbl);
                    mma_bf16(acc[mt][nt], fal[mt], fbh);
                }
            }
        }
        __syncthreads();
        if (c + 2 < NCH)
            g_load_stage(sbase, s, m0, n0, (c + 2) * BKH, tid, Ahi, Alo, Bhi, Blo);
    }

    #pragma unroll
    for (int mt = 0; mt < 2; ++mt) {
        #pragma unroll
        for (int nt = 0; nt < 8; ++nt) {
            int m = m0 + wm * 32 + mt * 16 + fr;
            int n = n0 + wn * 64 + nt * 8 + fc;
            float b0 = bias[n], b1 = bias[n + 1];
            float2 v0 = make_float2(acc[mt][nt][0] + b0, acc[mt][nt][1] + b1);
            float2 v1 = make_float2(acc[mt][nt][2] + b0, acc[mt][nt][3] + b1);
            *(float2*)(C + (u64)m * GM_N + n) = v0;
            *(float2*)(C + (u64)(m + 8) * GM_N + n) = v1;
        }
    }
}

// ============================================================================
// RMSNorm + rotary; emits bf16 hi/lo in [bh][l][d] layout (no fp32 output).
// One warp per (b,l,h). Warps [0,BL*H) -> Q, rest -> K.
// ============================================================================
__global__ __launch_bounds__(256) void normrope_kernel(
    const float* __restrict__ Q, const float* __restrict__ Kb,
    __nv_bfloat16* __restrict__ Qhi, __nv_bfloat16* __restrict__ Qlo,
    __nv_bfloat16* __restrict__ Khi, __nv_bfloat16* __restrict__ Klo,
    const float* __restrict__ cosp, const float* __restrict__ sinp)
{
    int gw = blockIdx.x * 8 + (threadIdx.x >> 5);
    int lane = threadIdx.x & 31;
    bool isQ = (gw < BL_ * H_);
    const float* X = isQ ? Q : Kb;
    __nv_bfloat16* OH = isQ ? Qhi : Khi;
    __nv_bfloat16* OL = isQ ? Qlo : Klo;
    int w = gw % (BL_ * H_);
    int row = w / H_;          // b*L + l
    int h   = w % H_;
    int b   = row >> 10;
    int l   = row & (L_ - 1);
    const float* x = X + (u64)row * E_ + h * D_;

    float v0 = x[lane], v1 = x[lane+32], v2 = x[lane+64], v3 = x[lane+96];
    float ss = v0*v0 + v1*v1 + v2*v2 + v3*v3;
    #pragma unroll
    for (int o = 16; o; o >>= 1) ss += __shfl_xor_sync(0xffffffffu, ss, o);
    float r = rsqrtf(ss * (1.0f / 128.0f) + 1e-6f);
    v0 *= r; v1 *= r; v2 *= r; v3 *= r;

    float c0 = cosp[l*64 + lane],      s0 = sinp[l*64 + lane];
    float c1 = cosp[l*64 + lane + 32], s1 = sinp[l*64 + lane + 32];
    float y0 = v0 * c0 - v2 * s0;   // pos lane
    float y2 = v0 * s0 + v2 * c0;   // pos lane+64
    float y1 = v1 * c1 - v3 * s1;   // pos lane+32
    float y3 = v1 * s1 + v3 * c1;   // pos lane+96

    u64 base = ((u64)(b * H_ + h) * L_ + l) * D_;
    unsigned short hh, ll;
    split1(y0, hh, ll); OH[base + lane]      = __ushort_as_bfloat16(hh); OL[base + lane]      = __ushort_as_bfloat16(ll);
    split1(y1, hh, ll); OH[base + lane + 32] = __ushort_as_bfloat16(hh); OL[base + lane + 32] = __ushort_as_bfloat16(ll);
    split1(y2, hh, ll); OH[base + lane + 64] = __ushort_as_bfloat16(hh); OL[base + lane + 64] = __ushort_as_bfloat16(ll);
    split1(y3, hh, ll); OH[base + lane + 96] = __ushort_as_bfloat16(hh); OL[base + lane + 96] = __ushort_as_bfloat16(ll);
}

// ============================================================================
// V transpose+split: g_V [bl][h*128+d] -> Vt hi/lo [bh][d][l]
// CTA: (bh, l-block of 32). 256 threads.
// ============================================================================
__global__ __launch_bounds__(256) void vsplit_kernel(
    const float* __restrict__ V,
    __nv_bfloat16* __restrict__ Vthi, __nv_bfloat16* __restrict__ Vtlo)
{
    __shared__ float tile[32][132];
    const int bh = blockIdx.x;
    const int l0 = blockIdx.y * 32;
    const int b = bh >> 4, h = bh & 15;
    const int tid = threadIdx.x;

    #pragma unroll
    for (int i = 0; i < 16; ++i) {
        int id = tid + i * 256;           // 4096 = 32 l x 128 d
        int l = id >> 7, d = id & 127;
        tile[l][d] = V[((u64)(b * L_ + l0 + l)) * E_ + h * D_ + d];
    }
    __syncthreads();
    #pragma unroll
    for (int i = 0; i < 16; ++i) {
        int id = tid + i * 256;
        int d = id >> 5, l = id & 31;
        float v = tile[l][d];
        unsigned short hh, ll;
        split1(v, hh, ll);
        u64 o = ((u64)bh * D_ + d) * L_ + l0 + l;
        Vthi[o] = __ushort_as_bfloat16(hh);
        Vtlo[o] = __ushort_as_bfloat16(ll);
    }
}

// ============================================================================
// scores mma: S[bh,i,j] = (Q . K) * scale. K-dim = 128 (one shot, no pipe).
// Tiles 128x128, 8 warps (4m x 2n). SMEM rows padded to 136 halves.
// ============================================================================
#define SROWP 136
#define STILE_H (128 * SROWP)               // 17408 halves per array
#define SMEM_SC_BYTES (4 * STILE_H * 2)     // 139264

__global__ __launch_bounds__(256) void scores_mma_kernel(
    const __nv_bfloat16* __restrict__ Qhi, const __nv_bfloat16* __restrict__ Qlo,
    const __nv_bfloat16* __restrict__ Khi, const __nv_bfloat16* __restrict__ Klo,
    float* __restrict__ S)
{
    const int j0 = blockIdx.x * 128;
    const int i0 = blockIdx.y * 128;
    if (j0 > i0) return;
    const int bh = blockIdx.z;

    extern __shared__ __align__(16) __nv_bfloat16 sh[];
    const u32 sbase = (u32)__cvta_generic_to_shared(sh);
    const int tid = threadIdx.x;
    const int warp = tid >> 5, lane = tid & 31;
    const int wm = warp & 3, wn = warp >> 2;

    // load Q tile (hi+lo) and K tile (hi+lo)
    #pragma unroll
    for (int i = 0; i < 8; ++i) {
        int id = tid + i * 256;            // 2048: 128 rows x 16 segs
        int r = id >> 4, sg = id & 15;
        u32 doff = (u32)(r * SROWP + sg * 8) * 2;
        u64 qo = ((u64)bh * L_ + i0 + r) * D_ + sg * 8;
        u64 ko = ((u64)bh * L_ + j0 + r) * D_ + sg * 8;
        cp16(sbase + doff, Qhi + qo);
        cp16(sbase + STILE_H * 2 + doff, Qlo + qo);
        cp16(sbase + STILE_H * 4 + doff, Khi + ko);
        cp16(sbase + STILE_H * 6 + doff, Klo + ko);
    }
    asm volatile("cp.async.commit_group;" ::: "memory");

    float acc[2][8][4];
    #pragma unroll
    for (int i = 0; i < 2; i++)
        #pragma unroll
        for (int j = 0; j < 8; j++)
            #pragma unroll
            for (int k = 0; k < 4; k++) acc[i][j][k] = 0.f;

    asm volatile("cp.async.wait_group 0;" ::: "memory");
    __syncthreads();

    const int fr = lane >> 2;
    const int fc = (lane & 3) * 2;
    const __nv_bfloat16* aH = sh + (wm * 32 + fr) * SROWP + fc;
    const __nv_bfloat16* aL = aH + STILE_H;
    const __nv_bfloat16* bH = sh + 2 * STILE_H + (wn * 64 + fr) * SROWP + fc;
    const __nv_bfloat16* bL = bH + STILE_H;

    #pragma unroll
    for (int kk = 0; kk < 128; kk += 16) {
        u32 fah[2][4], fal[2][4];
        #pragma unroll
        for (int mt = 0; mt < 2; ++mt) {
            const __nv_bfloat16* p = aH + mt * 16 * SROWP + kk;
            fah[mt][0] = *(const u32*)(p);
            fah[mt][1] = *(const u32*)(p + 8 * SROWP);
            fah[mt][2] = *(const u32*)(p + 8);
            fah[mt][3] = *(const u32*)(p + 8 * SROWP + 8);
            const __nv_bfloat16* q = aL + mt * 16 * SROWP + kk;
            fal[mt][0] = *(const u32*)(q);
            fal[mt][1] = *(const u32*)(q + 8 * SROWP);
            fal[mt][2] = *(const u32*)(q + 8);
            fal[mt][3] = *(const u32*)(q + 8 * SROWP + 8);
        }
        #pragma unroll
        for (int nt = 0; nt < 8; ++nt) {
            u32 fbh[2], fbl[2];
            const __nv_bfloat16* p = bH + nt * 8 * SROWP + kk;
            fbh[0] = *(const u32*)(p);
            fbh[1] = *(const u32*)(p + 8);
            const __nv_bfloat16* q = bL + nt * 8 * SROWP + kk;
            fbl[0] = *(const u32*)(q);
            fbl[1] = *(const u32*)(q + 8);
            #pragma unroll
            for (int mt = 0; mt < 2; ++mt) {
                mma_bf16(acc[mt][nt], fah[mt], fbh);
                mma_bf16(acc[mt][nt], fah[mt], fbl);
                mma_bf16(acc[mt][nt], fal[mt], fbh);
            }
        }
    }

    float* Sh = S + (u64)bh * L_ * L_;
    #pragma unroll
    for (int mt = 0; mt < 2; ++mt) {
        #pragma unroll
        for (int nt = 0; nt < 8; ++nt) {
            int m = i0 + wm * 32 + mt * 16 + fr;
            int n = j0 + wn * 64 + nt * 8 + fc;
            float2 v0 = make_float2(acc[mt][nt][0] * SCALE_, acc[mt][nt][1] * SCALE_);
            float2 v1 = make_float2(acc[mt][nt][2] * SCALE_, acc[mt][nt][3] * SCALE_);
            *(float2*)(Sh + (u64)m * L_ + n) = v0;
            *(float2*)(Sh + (u64)(m + 8) * L_ + n) = v1;
        }
    }
}

// ============================================================================
// Causal softmax -> bf16 hi/lo P (full rows, zero beyond diagonal)
// ============================================================================
__global__ __launch_bounds__(256) void softmax_kernel(
    const float* __restrict__ S,
    __nv_bfloat16* __restrict__ Phi, __nv_bfloat16* __restrict__ Plo)
{
    const int row = blockIdx.x;            // bh*L + i
    const int i = row & (L_ - 1);
    const int n = i + 1;
    const float* Sr = S + (u64)row * L_;
    __nv_bfloat16* PH = Phi + (u64)row * L_;
    __nv_bfloat16* PL = Plo + (u64)row * L_;
    const int tid = threadIdx.x;
    const int lane = tid & 31, wid = tid >> 5;
    __shared__ float red[8];

    float pm = -3.0e38f;
    for (int j = tid; j < n; j += 256) pm = fmaxf(pm, Sr[j]);
    #pragma unroll
    for (int o = 16; o; o >>= 1) pm = fmaxf(pm, __shfl_xor_sync(0xffffffffu, pm, o));
    if (lane == 0) red[wid] = pm;
    __syncthreads();
    if (tid == 0) {
        float m = red[0];
        #pragma unroll
        for (int k = 1; k < 8; k++) m = fmaxf(m, red[k]);
        red[0] = m;
    }
    __syncthreads();
    const float m = red[0];
    __syncthreads();

    float e[4];
    int c = 0;
    float ps = 0.f;
    for (int j = tid; j < n; j += 256) {
        float v = __expf(Sr[j] - m);
        e[c++] = v;
        ps += v;
    }
    #pragma unroll
    for (int o = 16; o; o >>= 1) ps += __shfl_xor_sync(0xffffffffu, ps, o);
    if (lane == 0) red[wid] = ps;
    __syncthreads();
    if (tid == 0) {
        float s = 0.f;
        #pragma unroll
        for (int k = 0; k < 8; k++) s += red[k];
        red[0] = s;
    }
    __syncthreads();
    const float inv = 1.0f / red[0];

    c = 0;
    for (int j = tid; j < n; j += 256) {
        unsigned short hh, ll;
        split1(e[c++] * inv, hh, ll);
        PH[j] = __ushort_as_bfloat16(hh);
        PL[j] = __ushort_as_bfloat16(ll);
    }
    for (int j = tid; j < L_; j += 256)
        if (j >= n) { PH[j] = __ushort_as_bfloat16(0); PL[j] = __ushort_as_bfloat16(0); }
}

// ============================================================================
// PV mma: O[bh,i,d] = sum_j P[i,j] Vt[d,j]. BK=64, double-buffered.
// M=128 (i), N=128 (d). Causal truncation: chunks = 2*(it+1).
// ============================================================================
#define PROWP 72
#define PTILE_H (128 * PROWP)                 // 9216 halves
#define PSTAGE_H (4 * PTILE_H)                // 36864
#define SMEM_PV_BYTES (2 * PSTAGE_H * 2)      // 147456

__device__ __forceinline__ void pv_load_stage(
    u32 sbase, int s, int bh, int i0, int k0, int tid,
    const __nv_bfloat16* __restrict__ Phi, const __nv_bfloat16* __restrict__ Plo,
    const __nv_bfloat16* __restrict__ Vthi, const __nv_bfloat16* __restrict__ Vtlo)
{
    u32 st = sbase + (u32)s * (PSTAGE_H * 2);
    #pragma unroll
    for (int i = 0; i < 4; ++i) {
        int id = tid + i * 256;           // 1024: 128 rows x 8 segs
        int r = id >> 3, sg = id & 7;
        u32 doff = (u32)(r * PROWP + sg * 8) * 2;
        u64 po = ((u64)bh * L_ + i0 + r) * L_ + k0 + sg * 8;
        u64 vo = ((u64)bh * D_ + r) * L_ + k0 + sg * 8;
        cp16(st + doff, Phi + po);
        cp16(st + PTILE_H * 2 + doff, Plo + po);
        cp16(st + PTILE_H * 4 + doff, Vthi + vo);
        cp16(st + PTILE_H * 6 + doff, Vtlo + vo);
    }
    asm volatile("cp.async.commit_group;" ::: "memory");
}

__global__ __launch_bounds__(256) void pv_mma_kernel(
    const __nv_bfloat16* __restrict__ Phi, const __nv_bfloat16* __restrict__ Plo,
    const __nv_bfloat16* __restrict__ Vthi, const __nv_bfloat16* __restrict__ Vtlo,
    float* __restrict__ O)
{
    extern __shared__ __align__(16) __nv_bfloat16 sh[];
    const int bh = blockIdx.z;
    const int i0 = blockIdx.y * 128;
    const int b = bh >> 4, h = bh & 15;
    const int tid = threadIdx.x;
    const int warp = tid >> 5, lane = tid & 31;
    const int wm = warp & 3, wn = warp >> 2;
    const u32 sbase = (u32)__cvta_generic_to_shared(sh);
    const int nch = 2 * (blockIdx.y + 1);

    float acc[2][8][4];
    #pragma unroll
    for (int i = 0; i < 2; i++)
        #pragma unroll
        for (int j = 0; j < 8; j++)
            #pragma unroll
            for (int k = 0; k < 4; k++) acc[i][j][k] = 0.f;

    pv_load_stage(sbase, 0, bh, i0, 0,  tid, Phi, Plo, Vthi, Vtlo);
    pv_load_stage(sbase, 1, bh, i0, 64, tid, Phi, Plo, Vthi, Vtlo);

    const int fr = lane >> 2;
    const int fc = (lane & 3) * 2;

    for (int c = 0; c < nch; ++c) {
        const int s = c & 1;
        if (c < nch - 1) asm volatile("cp.async.wait_group 1;" ::: "memory");
        else             asm volatile("cp.async.wait_group 0;" ::: "memory");
        __syncthreads();

        const __nv_bfloat16* sS = sh + s * PSTAGE_H;
        const __nv_bfloat16* aH = sS + (wm * 32 + fr) * PROWP + fc;
        const __nv_bfloat16* aL = aH + PTILE_H;
        const __nv_bfloat16* bH = sS + 2 * PTILE_H + (wn * 64 + fr) * PROWP + fc;
        const __nv_bfloat16* bL = bH + PTILE_H;

        #pragma unroll
        for (int kk = 0; kk < 64; kk += 16) {
            u32 fah[2][4], fal[2][4];
            #pragma unroll
            for (int mt = 0; mt < 2; ++mt) {
                const __nv_bfloat16* p = aH + mt * 16 * PROWP + kk;
                fah[mt][0] = *(const u32*)(p);
                fah[mt][1] = *(const u32*)(p + 8 * PROWP);
                fah[mt][2] = *(const u32*)(p + 8);
                fah[mt][3] = *(const u32*)(p + 8 * PROWP + 8);
                const __nv_bfloat16* q = aL + mt * 16 * PROWP + kk;
                fal[mt][0] = *(const u32*)(q);
                fal[mt][1] = *(const u32*)(q + 8 * PROWP);
                fal[mt][2] = *(const u32*)(q + 8);
                fal[mt][3] = *(const u32*)(q + 8 * PROWP + 8);
            }
            #pragma unroll
            for (int nt = 0; nt < 8; ++nt) {
                u32 fbh[2], fbl[2];
                const __nv_bfloat16* p = bH + nt * 8 * PROWP + kk;
                fbh[0] = *(const u32*)(p);
                fbh[1] = *(const u32*)(p + 8);
                const __nv_bfloat16* q = bL + nt * 8 * PROWP + kk;
                fbl[0] = *(const u32*)(q);
                fbl[1] = *(const u32*)(q + 8);
                #pragma unroll
                for (int mt = 0; mt < 2; ++mt) {
                    mma_bf16(acc[mt][nt], fah[mt], fbh);
                    mma_bf16(acc[mt][nt], fah[mt], fbl);
                    mma_bf16(acc[mt][nt], fal[mt], fbh);
                }
            }
        }
        __syncthreads();
        if (c + 2 < nch)
            pv_load_stage(sbase, s, bh, i0, (c + 2) * 64, tid, Phi, Plo, Vthi, Vtlo);
    }

    #pragma unroll
    for (int mt = 0; mt < 2; ++mt) {
        #pragma unroll
        for (int nt = 0; nt < 8; ++nt) {
            int m = i0 + wm * 32 + mt * 16 + fr;        // l index
            int n = wn * 64 + nt * 8 + fc;              // d index
            float2 v0 = make_float2(acc[mt][nt][0], acc[mt][nt][1]);
            float2 v1 = make_float2(acc[mt][nt][2], acc[mt][nt][3]);
            *(float2*)(O + ((u64)(b * L_ + m) * E_) + h * D_ + n) = v0;
            *(float2*)(O + ((u64)(b * L_ + m + 8) * E_) + h * D_ + n) = v1;
        }
    }
}

// ============================================================================
// v-orthogonalization (unchanged)
// ============================================================================
__global__ __launch_bounds__(256) void ortho_kernel(
    float* __restrict__ O, const float* __restrict__ V)
{
    int gw = blockIdx.x * 8 + (threadIdx.x >> 5);
    int lane = threadIdx.x & 31;
    int row = gw / H_;
    int h = gw % H_;
    float* o = O + (u64)row * E_ + h * D_;
    const float* v = V + (u64)row * E_ + h * D_;

    float ov[4], vv[4];
    #pragma unroll
    for (int k = 0; k < 4; k++) { ov[k] = o[lane + 32*k]; vv[k] = v[lane + 32*k]; }
    float ss = 0.f, sv = 0.f;
    #pragma unroll
    for (int k = 0; k < 4; k++) { ss = fmaf(vv[k], vv[k], ss); sv = fmaf(ov[k], vv[k], sv); }
    #pragma unroll
    for (int off = 16; off; off >>= 1) {
        ss += __shfl_xor_sync(0xffffffffu, ss, off);
        sv += __shfl_xor_sync(0xffffffffu, sv, off);
    }
    float vnorm = sqrtf(ss);
    float inv = 1.0f / fmaxf(vnorm, 1e-9f);
    float coef = sv * inv * inv;
    #pragma unroll
    for (int k = 0; k < 4; k++) o[lane + 32*k] = ov[k] - coef * vv[k];
}

// ============================================================================
extern "C" void kernel_launch(void* const* d_in, const int* in_sizes, int n_in,
                              void* d_out, int out_size)
{
    const float* query = (const float*)d_in[0];
    const float* key   = (const float*)d_in[1];
    const float* value = (const float*)d_in[2];
    const float* cosp  = (const float*)d_in[4];
    const float* sinp  = (const float*)d_in[5];
    const float* Wq = (const float*)d_in[6];
    const float* bq = (const float*)d_in[7];
    const float* Wk = (const float*)d_in[8];
    const float* bk = (const float*)d_in[9];
    const float* Wv = (const float*)d_in[10];
    const float* bv = (const float*)d_in[11];
    const float* Wo = (const float*)d_in[12];
    const float* bo = (const float*)d_in[13];
    float* out = (float*)d_out;

    float *gQ, *gK, *gV, *gO, *gS;
    __nv_bfloat16 *gAhi, *gAlo, *gWhi, *gWlo;
    __nv_bfloat16 *gQhi, *gQlo, *gKhi, *gKlo, *gVthi, *gVtlo, *gPhi, *gPlo;
    cudaGetSymbolAddress((void**)&gQ, g_Q);
    cudaGetSymbolAddress((void**)&gK, g_K);
    cudaGetSymbolAddress((void**)&gV, g_V);
    cudaGetSymbolAddress((void**)&gO, g_O);
    cudaGetSymbolAddress((void**)&gS, g_S);
    cudaGetSymbolAddress((void**)&gAhi, g_Ahi);
    cudaGetSymbolAddress((void**)&gAlo, g_Alo);
    cudaGetSymbolAddress((void**)&gWhi, g_Whi);
    cudaGetSymbolAddress((void**)&gWlo, g_Wlo);
    cudaGetSymbolAddress((void**)&gQhi, g_Qhi);
    cudaGetSymbolAddress((void**)&gQlo, g_Qlo);
    cudaGetSymbolAddress((void**)&gKhi, g_Khi);
    cudaGetSymbolAddress((void**)&gKlo, g_Klo);
    cudaGetSymbolAddress((void**)&gVthi, g_Vthi);
    cudaGetSymbolAddress((void**)&gVtlo, g_Vtlo);
    cudaGetSymbolAddress((void**)&gPhi, g_Phi);
    cudaGetSymbolAddress((void**)&gPlo, g_Plo);

    cudaFuncSetAttribute(gemm_mma_kernel, cudaFuncAttributeMaxDynamicSharedMemorySize,
                         SMEM_GEMM_BYTES);
    cudaFuncSetAttribute(scores_mma_kernel, cudaFuncAttributeMaxDynamicSharedMemorySize,
                         SMEM_SC_BYTES);
    cudaFuncSetAttribute(pv_mma_kernel, cudaFuncAttributeMaxDynamicSharedMemorySize,
                         SMEM_PV_BYTES);

    const dim3 blk(256);
    const int nAct = BL_ * E_;
    const int nW   = E_ * E_;
    const dim3 gGemm(GM_N / 128, GM_M / 128);

    // Q projection
    split_kernel<<<nAct / 1024, blk>>>(query, gAhi, gAlo, nAct);
    split_kernel<<<nW / 1024, blk>>>(Wq, gWhi, gWlo, nW);
    gemm_mma_kernel<<<gGemm, blk, SMEM_GEMM_BYTES>>>(gAhi, gAlo, gWhi, gWlo, bq, gQ);
    // K projection
    split_kernel<<<nAct / 1024, blk>>>(key, gAhi, gAlo, nAct);
    split_kernel<<<nW / 1024, blk>>>(Wk, gWhi, gWlo, nW);
    gemm_mma_kernel<<<gGemm, blk, SMEM_GEMM_BYTES>>>(gAhi, gAlo, gWhi, gWlo, bk, gK);
    // V projection
    split_kernel<<<nAct / 1024, blk>>>(value, gAhi, gAlo, nAct);
    split_kernel<<<nW / 1024, blk>>>(Wv, gWhi, gWlo, nW);
    gemm_mma_kernel<<<gGemm, blk, SMEM_GEMM_BYTES>>>(gAhi, gAlo, gWhi, gWlo, bv, gV);

    // norm+rope -> bf16 hi/lo [bh][l][d]; V -> transposed hi/lo [bh][d][l]
    normrope_kernel<<<(2 * BL_ * H_) / 8, blk>>>(gQ, gK, gQhi, gQlo, gKhi, gKlo, cosp, sinp);
    vsplit_kernel<<<dim3(BH_, L_ / 32), blk>>>(gV, gVthi, gVtlo);

    scores_mma_kernel<<<dim3(L_ / 128, L_ / 128, BH_), blk, SMEM_SC_BYTES>>>(
        gQhi, gQlo, gKhi, gKlo, gS);
    softmax_kernel<<<BH_ * L_, blk>>>(gS, gPhi, gPlo);
    pv_mma_kernel<<<dim3(1, L_ / 128, BH_), blk, SMEM_PV_BYTES>>>(
        gPhi, gPlo, gVthi, gVtlo, gO);
    ortho_kernel<<<(BL_ * H_) / 8, blk>>>(gO, gV);

    // Output projection
    split_kernel<<<nAct / 1024, blk>>>(gO, gAhi, gAlo, nAct);
    split_kernel<<<nW / 1024, blk>>>(Wo, gWhi, gWlo, nW);
    gemm_mma_kernel<<<gGemm, blk, SMEM_GEMM_BYTES>>>(gAhi, gAlo, gWhi, gWlo, bo, out);
}